// round 3
// baseline (speedup 1.0000x reference)
#include <cuda_runtime.h>

#define BATCH 4
#define NPIX 4096
#define EPS 1e-6f
#define ATTN_SCALE 0.0625f   // 1/sqrt(256)
#define FULLMASK 0xFFFFFFFFu

typedef unsigned long long ull;

// ---------------- scratch (device globals: allocation-free) ----------------
__device__ float g_edge32[BATCH * 128 * 1024];
__device__ float g_fused32[BATCH * 128 * 1024];
__device__ float g_edge_up[BATCH * 128 * NPIX];
__device__ float g_fused_up[BATCH * 128 * NPIX];
__device__ float g_sim[BATCH * NPIX];
__device__ float g_l2e[BATCH * NPIX];
__device__ float g_density[BATCH * NPIX];
__device__ float g_q[BATCH * NPIX * 256];
__device__ float g_k[BATCH * NPIX * 256];
__device__ float g_v[BATCH * NPIX * 256];
__device__ float g_ao[BATCH * NPIX * 256];
__device__ float g_wq2D[128 * 512];   // folded w_q, [c][2o] dup
__device__ float g_wkD[256 * 512];    // w_k [c][2o] dup
__device__ float g_wfD[256 * 256];    // w_fusion [c][2o] dup
__device__ float g_walD[64 * 256];    // w_align [c][2o] dup
__device__ float g_wfalD[128 * 256];  // w_fused_align [c][2o] dup

// ---------------- f32x2 packed FMA ----------------
__device__ __forceinline__ ull ffma2(ull a, ull b, ull c) {
    ull d;
    asm("fma.rn.f32x2 %0, %1, %2, %3;" : "=l"(d) : "l"(a), "l"(b), "l"(c));
    return d;
}
__device__ __forceinline__ float2 u2f(ull u) {
    union { ull u; float2 f; } t; t.u = u; return t.f;
}
__device__ __forceinline__ ull fdup(float x) {
    union { ull u; float2 f; } t; t.f.x = x; t.f.y = x; return t.u;
}

// ---------------- weight prep: fold/transpose/duplicate everything ----------------
__global__ void prep_weights_kernel(const float* __restrict__ w_q,
                                    const float* __restrict__ w_k,
                                    const float* __restrict__ w_f,
                                    const float* __restrict__ w_al,
                                    const float* __restrict__ w_fal) {
    int i = blockIdx.x * 256 + threadIdx.x;   // 0..65535
    int o = i >> 8, c = i & 255;
    float vk = w_k[o * 256 + c];
    g_wkD[c * 512 + 2 * o] = vk;
    g_wkD[c * 512 + 2 * o + 1] = vk;
    if (c < 128) {
        float vq = w_q[o * 256 + c] + w_q[o * 256 + 128 + c];
        g_wq2D[c * 512 + 2 * o] = vq;
        g_wq2D[c * 512 + 2 * o + 1] = vq;
    }
    if (o < 128) {
        float vf = w_f[o * 256 + c];
        g_wfD[c * 256 + 2 * o] = vf;
        g_wfD[c * 256 + 2 * o + 1] = vf;
        if (c < 64) {
            float v = w_al[o * 64 + c];
            g_walD[c * 256 + 2 * o] = v;
            g_walD[c * 256 + 2 * o + 1] = v;
        }
        if (c < 128) {
            float v = w_fal[o * 128 + c];
            g_wfalD[c * 256 + 2 * o] = v;
            g_wfalD[c * 256 + 2 * o + 1] = v;
        }
    }
}

// ---------------- 1x1 conv at 32x32, smem-tiled GEMM ----------------
__global__ __launch_bounds__(256) void conv_tile_kernel(const float* __restrict__ x,
                                                        const float* __restrict__ bias,
                                                        int Cin, int which) {
    __shared__ float xs[32 * 64];
    int b = blockIdx.y, p0 = blockIdx.x * 64, t = threadIdx.x;
    int o = t & 127, ph = t >> 7;  // ph: 0/1 -> pixels [ph*32, ph*32+32)
    const float* wD = which ? g_wfalD : g_walD;
    ull acc[16];
    ull bo = fdup(bias[o]);
#pragma unroll
    for (int j = 0; j < 16; j++) acc[j] = bo;
    int nch = Cin >> 5;
    for (int cc = 0; cc < nch; cc++) {
        __syncthreads();
#pragma unroll
        for (int it = 0; it < 8; it++) {
            int idx = it * 256 + t;
            int c = idx >> 6, p = idx & 63;
            xs[idx] = x[(size_t)(b * Cin + cc * 32 + c) * 1024 + p0 + p];
        }
        __syncthreads();
#pragma unroll 4
        for (int c = 0; c < 32; c++) {
            ull w = *(const ull*)&wD[(cc * 32 + c) * 256 + 2 * o];
            const ulonglong2* row = (const ulonglong2*)&xs[c * 64 + ph * 32];
#pragma unroll
            for (int j = 0; j < 8; j++) {
                ulonglong2 v = row[j];
                acc[2 * j] = ffma2(w, v.x, acc[2 * j]);
                acc[2 * j + 1] = ffma2(w, v.y, acc[2 * j + 1]);
            }
        }
    }
    float* out = which ? g_fused32 : g_edge32;
    size_t ob = (size_t)(b * 128 + o) * 1024 + p0 + ph * 32;
#pragma unroll
    for (int j = 0; j < 16; j++) *(ull*)&out[ob + 2 * j] = acc[j];
}

// ---------------- fused bilinear upsample (32->64) + l2/cosine sim ----------------
__global__ void upsample_sim_kernel(const float* __restrict__ sem) {
    int b = blockIdx.y;
    int n = blockIdx.x * 256 + threadIdx.x;
    int x = n >> 6, y = n & 63;
    float sx = x * 0.5f - 0.25f;
    int ix = (int)floorf(sx);
    float fx = sx - (float)ix;
    int x0 = min(max(ix, 0), 31), x1 = min(max(ix + 1, 0), 31);
    float sy = y * 0.5f - 0.25f;
    int iy = (int)floorf(sy);
    float fy = sy - (float)iy;
    int y0 = min(max(iy, 0), 31), y1 = min(max(iy + 1, 0), 31);
    float w00 = (1.f - fx) * (1.f - fy), w01 = (1.f - fx) * fy;
    float w10 = fx * (1.f - fy), w11 = fx * fy;
    int i00 = x0 * 32 + y0, i01 = x0 * 32 + y1;
    int i10 = x1 * 32 + y0, i11 = x1 * 32 + y1;
    size_t ib = (size_t)b * 128 * 1024;
    size_t obase = (size_t)b * 128 * NPIX + n;
    float se = 0.f, ss = 0.f, dt = 0.f;
    for (int c = 0; c < 128; c++) {
        const float* e = g_edge32 + ib + (size_t)c * 1024;
        float ve = w00 * e[i00] + w01 * e[i01] + w10 * e[i10] + w11 * e[i11];
        const float* f = g_fused32 + ib + (size_t)c * 1024;
        float vf = w00 * f[i00] + w01 * f[i01] + w10 * f[i10] + w11 * f[i11];
        g_edge_up[obase + (size_t)c * NPIX] = ve;
        g_fused_up[obase + (size_t)c * NPIX] = vf;
        float s = sem[obase + (size_t)c * NPIX];
        se = fmaf(ve, ve, se);
        ss = fmaf(s, s, ss);
        dt = fmaf(ve, s, dt);
    }
    float le = sqrtf(se), ls = sqrtf(ss);
    g_l2e[b * NPIX + n] = le;
    g_sim[b * NPIX + n] = (dt / ((le + EPS) * (ls + EPS)) + 1.f) * 0.5f;
}

// ---------------- per-batch softmax over 4096 -> density ----------------
__global__ void density_kernel() {
    int b = blockIdx.x, t = threadIdx.x;
    int lane = t & 31, wid = t >> 5;
    __shared__ float smx[32], ssm[32];
    float v[4];
#pragma unroll
    for (int i = 0; i < 4; i++) v[i] = g_l2e[b * NPIX + t + i * 1024];
    float mx = fmaxf(fmaxf(v[0], v[1]), fmaxf(v[2], v[3]));
#pragma unroll
    for (int off = 16; off; off >>= 1) mx = fmaxf(mx, __shfl_xor_sync(FULLMASK, mx, off));
    if (!lane) smx[wid] = mx;
    __syncthreads();
    if (wid == 0) {
        float m = smx[lane];
#pragma unroll
        for (int off = 16; off; off >>= 1) m = fmaxf(m, __shfl_xor_sync(FULLMASK, m, off));
        smx[lane] = m;
    }
    __syncthreads();
    mx = smx[0];
    float e[4], s = 0.f;
#pragma unroll
    for (int i = 0; i < 4; i++) { e[i] = expf(v[i] - mx); s += e[i]; }
#pragma unroll
    for (int off = 16; off; off >>= 1) s += __shfl_xor_sync(FULLMASK, s, off);
    if (!lane) ssm[wid] = s;
    __syncthreads();
    if (wid == 0) {
        float x = ssm[lane];
#pragma unroll
        for (int off = 16; off; off >>= 1) x += __shfl_xor_sync(FULLMASK, x, off);
        ssm[lane] = x;
    }
    __syncthreads();
    float sc = 4096.f / ssm[0];
#pragma unroll
    for (int i = 0; i < 4; i++) g_density[b * NPIX + t + i * 1024] = e[i] * sc;
}

// ---------------- build V = concat(sem_raw, fused) pixel-major ----------------
__global__ void vbuild_kernel(const float* __restrict__ sem) {
    __shared__ float tile[32][33];
    int b = blockIdx.z;
    int n0 = blockIdx.x * 32;
    int cb = blockIdx.y;  // 0..7 (0-3: sem, 4-7: fused)
    int c0 = cb * 32;
    const float* src = (cb < 4) ? (sem + ((size_t)b * 128 + c0) * NPIX)
                                : (g_fused_up + ((size_t)b * 128 + (c0 - 128)) * NPIX);
    int tx = threadIdx.x, ty = threadIdx.y;
    for (int i = ty; i < 32; i += 8)
        tile[i][tx] = src[(size_t)i * NPIX + n0 + tx];
    __syncthreads();
    for (int i = ty; i < 32; i += 8)
        g_v[((size_t)b * NPIX + n0 + i) * 256 + c0 + tx] = tile[tx][i];
}

// ---------------- q projection: 64 pixels/block GEMM ----------------
__global__ __launch_bounds__(256, 2) void qk_q_kernel(const float* __restrict__ b_q) {
    __shared__ float sq[128 * 64];
    int b = blockIdx.y, n0 = blockIdx.x * 64, t = threadIdx.x;
#pragma unroll
    for (int it = 0; it < 32; it++) {
        int idx = it * 256 + t;
        int c = idx >> 6, nl = idx & 63;
        int n = n0 + nl;
        sq[idx] = g_edge_up[(size_t)(b * 128 + c) * NPIX + n] * g_sim[b * NPIX + n];
    }
    __syncthreads();
    ull acc[32];
    ull bq = fdup(b_q[t]);
#pragma unroll
    for (int j = 0; j < 32; j++) acc[j] = bq;
#pragma unroll 2
    for (int c = 0; c < 128; c++) {
        ull w = *(const ull*)&g_wq2D[c * 512 + 2 * t];
        const ulonglong2* row = (const ulonglong2*)&sq[c * 64];
#pragma unroll
        for (int j = 0; j < 16; j++) {
            ulonglong2 v = row[j];
            acc[2 * j] = ffma2(w, v.x, acc[2 * j]);
            acc[2 * j + 1] = ffma2(w, v.y, acc[2 * j + 1]);
        }
    }
    size_t ob = ((size_t)b * NPIX + n0) * 256 + t;
#pragma unroll
    for (int j = 0; j < 32; j++) {
        float2 f = u2f(acc[j]);
        g_q[ob + (size_t)(2 * j) * 256] = f.x;
        g_q[ob + (size_t)(2 * j + 1) * 256] = f.y;
    }
}

// ---------------- k projection: 64 pixels/block GEMM, c chunked ----------------
__global__ __launch_bounds__(256, 2) void qk_k_kernel(const float* __restrict__ sem,
                                                      const float* __restrict__ b_k) {
    __shared__ float sk[64 * 64];
    int b = blockIdx.y, n0 = blockIdx.x * 64, t = threadIdx.x;
    ull acc[32];
    ull bk = fdup(b_k[t]);
#pragma unroll
    for (int j = 0; j < 32; j++) acc[j] = bk;
    for (int cc = 0; cc < 4; cc++) {
        __syncthreads();
#pragma unroll
        for (int it = 0; it < 16; it++) {
            int idx = it * 256 + t;
            int c = idx >> 6, nl = idx & 63;
            int cg = cc * 64 + c;
            int n = n0 + nl;
            float v;
            if (cg < 128)
                v = sem[(size_t)(b * 128 + cg) * NPIX + n] * g_density[b * NPIX + n];
            else
                v = g_fused_up[(size_t)(b * 128 + cg - 128) * NPIX + n];
            sk[idx] = v;
        }
        __syncthreads();
#pragma unroll 2
        for (int c = 0; c < 64; c++) {
            ull w = *(const ull*)&g_wkD[(cc * 64 + c) * 512 + 2 * t];
            const ulonglong2* row = (const ulonglong2*)&sk[c * 64];
#pragma unroll
            for (int j = 0; j < 16; j++) {
                ulonglong2 v = row[j];
                acc[2 * j] = ffma2(w, v.x, acc[2 * j]);
                acc[2 * j + 1] = ffma2(w, v.y, acc[2 * j + 1]);
            }
        }
    }
    size_t ob = ((size_t)b * NPIX + n0) * 256 + t;
#pragma unroll
    for (int j = 0; j < 32; j++) {
        float2 f = u2f(acc[j]);
        g_k[ob + (size_t)(2 * j) * 256] = f.x;
        g_k[ob + (size_t)(2 * j + 1) * 256] = f.y;
    }
}

// ---------------- local windowed attention ----------------
// Query tile 8(x) x 4(y) = 32 q. Key window 18(x) x 14(y) = 252, padded to 256.
// Thread: warp=t>>5, lane: qg=lane&3 (q y-offset), kgl=lane>>2; kg=warp*8+kgl (4 keys each).
// Per thread: 8 q (qi = x-offset) x 4 k. q index packing in smem rows: qidx = qi*4+qg.
#define KV_F 8192                // 32 x 256
#define PS_STRIDE 66
#define PS_F (256 * PS_STRIDE)   // 16896
#define QS_STRIDE 68
#define QS_F (32 * QS_STRIDE)    // 2176
#define RED_F 288
#define ATTN_SMEM_BYTES ((KV_F + PS_F + QS_F + RED_F) * 4)

__global__ __launch_bounds__(256, 2) void attn_kernel() {
    extern __shared__ float sm[];
    float* KV = sm;                       // K chunk [32 c][256 ki] / V chunk [32 ki][256 ch]
    float* Ps = sm + KV_F;                // [256 ki][66]: dup pairs, q-packed qi*4+qg
    float* Qs = sm + KV_F + PS_F;         // [32 c][68]: dup pairs
    float* red = sm + KV_F + PS_F + QS_F; // [32 q][8 warps + pad]

    int t = threadIdx.x, b = blockIdx.y, tile = blockIdx.x;
    int qx0 = (tile >> 4) * 8, qy0 = (tile & 15) * 4;
    int warp = t >> 5, lane = t & 31;
    int qg = lane & 3, kgl = lane >> 2;
    int kg = warp * 8 + kgl;
    size_t kvbase = (size_t)b * NPIX * 256;

    // ---- QK ----
    ull accl[8][2];
#pragma unroll
    for (int qi = 0; qi < 8; qi++) { accl[qi][0] = 0ull; accl[qi][1] = 0ull; }

    for (int cc = 0; cc < 8; cc++) {
        __syncthreads();
        // K stage: one key row per thread, STS conflict-free (lane -> ki)
        {
            int ki = t;
            int kr = ki / 14, kc = ki - 14 * kr;
            int kx = min(max(qx0 - 5 + kr, 0), 63);
            int ky = min(max(qy0 - 5 + kc, 0), 63);
            const float* src = &g_k[kvbase + (size_t)((kx << 6) + ky) * 256 + cc * 32];
#pragma unroll
            for (int c4 = 0; c4 < 8; c4++) {
                float4 v = *(const float4*)(src + c4 * 4);
                KV[(c4 * 4 + 0) * 256 + ki] = v.x;
                KV[(c4 * 4 + 1) * 256 + ki] = v.y;
                KV[(c4 * 4 + 2) * 256 + ki] = v.z;
                KV[(c4 * 4 + 3) * 256 + ki] = v.w;
            }
        }
        // Q stage: dup pairs
#pragma unroll
        for (int it = 0; it < 4; it++) {
            int idx = it * 256 + t;
            int q = idx >> 5, c = idx & 31;
            int nq = ((qx0 + (q >> 2)) << 6) + qy0 + (q & 3);
            float qv = g_q[kvbase + (size_t)nq * 256 + cc * 32 + c] * ATTN_SCALE;
            Qs[c * QS_STRIDE + 2 * q] = qv;
            Qs[c * QS_STRIDE + 2 * q + 1] = qv;
        }
        __syncthreads();
#pragma unroll 4
        for (int c = 0; c < 32; c++) {
            ulonglong2 kk = *(const ulonglong2*)&KV[c * 256 + kg * 4];
            const float* qrow = &Qs[c * QS_STRIDE];
#pragma unroll
            for (int qi = 0; qi < 8; qi++) {
                ull qd = *(const ull*)&qrow[2 * (qi * 4 + qg)];
                accl[qi][0] = ffma2(qd, kk.x, accl[qi][0]);
                accl[qi][1] = ffma2(qd, kk.y, accl[qi][1]);
            }
        }
    }

    // ---- unpack + mask ----
    float lg[8][4];
    int krA[4];
    bool bok[4];
#pragma unroll
    for (int kj = 0; kj < 4; kj++) {
        int ki = kg * 4 + kj;
        int kr = ki / 14, kc = ki - 14 * kr;
        int kx = qx0 - 5 + kr, ky = qy0 - 5 + kc;
        krA[kj] = kr;
        bok[kj] = (ki < 252) && (kx >= 0) && (kx < 64) && (ky >= 0) && (ky < 64)
                  && (kc >= qg) && (kc <= qg + 10);
    }
#pragma unroll
    for (int qi = 0; qi < 8; qi++) {
        float2 a = u2f(accl[qi][0]), bb = u2f(accl[qi][1]);
        lg[qi][0] = a.x; lg[qi][1] = a.y; lg[qi][2] = bb.x; lg[qi][3] = bb.y;
#pragma unroll
        for (int kj = 0; kj < 4; kj++) {
            bool ok = bok[kj] && (krA[kj] >= qi) && (krA[kj] <= qi + 10);
            if (!ok) lg[qi][kj] = -1e30f;
        }
    }

    // ---- softmax (reduce across kgl within warp, then across warps) ----
    float mx[8];
#pragma unroll
    for (int qi = 0; qi < 8; qi++) {
        float m = fmaxf(fmaxf(lg[qi][0], lg[qi][1]), fmaxf(lg[qi][2], lg[qi][3]));
        m = fmaxf(m, __shfl_xor_sync(FULLMASK, m, 4));
        m = fmaxf(m, __shfl_xor_sync(FULLMASK, m, 8));
        m = fmaxf(m, __shfl_xor_sync(FULLMASK, m, 16));
        if (kgl == 0) red[(qi * 4 + qg) * 8 + warp] = m;
    }
    __syncthreads();
#pragma unroll
    for (int qi = 0; qi < 8; qi++) {
        float m = -1e30f;
#pragma unroll
        for (int w = 0; w < 8; w++) m = fmaxf(m, red[(qi * 4 + qg) * 8 + w]);
        mx[qi] = m;
    }
    __syncthreads();
    float pv[8][4];
#pragma unroll
    for (int qi = 0; qi < 8; qi++) {
        float s = 0.f;
#pragma unroll
        for (int kj = 0; kj < 4; kj++) {
            pv[qi][kj] = __expf(lg[qi][kj] - mx[qi]);
            s += pv[qi][kj];
        }
        s += __shfl_xor_sync(FULLMASK, s, 4);
        s += __shfl_xor_sync(FULLMASK, s, 8);
        s += __shfl_xor_sync(FULLMASK, s, 16);
        if (kgl == 0) red[(qi * 4 + qg) * 8 + warp] = s;
    }
    __syncthreads();
#pragma unroll
    for (int qi = 0; qi < 8; qi++) {
        float s = 0.f;
#pragma unroll
        for (int w = 0; w < 8; w++) s += red[(qi * 4 + qg) * 8 + w];
        float inv = 1.f / s;
#pragma unroll
        for (int kj = 0; kj < 4; kj++) {
            float p = pv[qi][kj] * inv;
            float* dst = &Ps[(kg * 4 + kj) * PS_STRIDE + 2 * (qi * 4 + qg)];
            dst[0] = p;
            dst[1] = p;
        }
    }

    // ---- AV ----
    ull acco[8][2];
#pragma unroll
    for (int qi = 0; qi < 8; qi++) { acco[qi][0] = 0ull; acco[qi][1] = 0ull; }

    for (int kc4 = 0; kc4 < 8; kc4++) {
        __syncthreads();
#pragma unroll
        for (int it = 0; it < 8; it++) {
            int idx = it * 256 + t;
            int kil = idx >> 6, cg = idx & 63;
            int ki = kc4 * 32 + kil;
            int kr = ki / 14, kc = ki - 14 * kr;
            int kx = min(max(qx0 - 5 + kr, 0), 63);
            int ky = min(max(qy0 - 5 + kc, 0), 63);
            *(float4*)&KV[kil * 256 + cg * 4] =
                *(const float4*)&g_v[kvbase + (size_t)((kx << 6) + ky) * 256 + cg * 4];
        }
        __syncthreads();
#pragma unroll 4
        for (int kil = 0; kil < 32; kil++) {
            ulonglong2 vv = *(const ulonglong2*)&KV[kil * 256 + kg * 4];
            const float* prow = &Ps[(kc4 * 32 + kil) * PS_STRIDE];
#pragma unroll
            for (int qi = 0; qi < 8; qi++) {
                ull pd = *(const ull*)&prow[2 * (qi * 4 + qg)];
                acco[qi][0] = ffma2(pd, vv.x, acco[qi][0]);
                acco[qi][1] = ffma2(pd, vv.y, acco[qi][1]);
            }
        }
    }

#pragma unroll
    for (int qi = 0; qi < 8; qi++) {
        int nq = ((qx0 + qi) << 6) + qy0 + qg;
        ull* dst = (ull*)&g_ao[kvbase + (size_t)nq * 256 + kg * 4];
        dst[0] = acco[qi][0];
        dst[1] = acco[qi][1];
    }
}

// ---------------- fusion 1x1 conv -> d_out [b,128,64,64] ----------------
__global__ __launch_bounds__(128) void fusion_kernel(const float* __restrict__ b_f,
                                                     float* __restrict__ out) {
    __shared__ float sin_[256 * 36];
    int b = blockIdx.y, n0 = blockIdx.x * 32, tid = threadIdx.x;
    for (int idx = tid; idx < 32 * 256; idx += 128) {
        int p = idx >> 8, c = idx & 255;
        sin_[c * 36 + p] = g_ao[((size_t)b * NPIX + n0 + p) * 256 + c];
    }
    __syncthreads();
    ull acc[16];
    ull bo = fdup(b_f[tid]);
#pragma unroll
    for (int j = 0; j < 16; j++) acc[j] = bo;
#pragma unroll 4
    for (int c = 0; c < 256; c++) {
        ull w = *(const ull*)&g_wfD[c * 256 + 2 * tid];
        const float* row = &sin_[c * 36];
#pragma unroll
        for (int j = 0; j < 8; j++) {
            ulonglong2 v = *(const ulonglong2*)&row[j * 4];
            acc[2 * j] = ffma2(w, v.x, acc[2 * j]);
            acc[2 * j + 1] = ffma2(w, v.y, acc[2 * j + 1]);
        }
    }
    __syncthreads();
#pragma unroll
    for (int j = 0; j < 16; j++) {
        float2 f = u2f(acc[j]);
        sin_[tid * 33 + 2 * j] = f.x;
        sin_[tid * 33 + 2 * j + 1] = f.y;
    }
    __syncthreads();
    for (int idx = tid; idx < 128 * 32; idx += 128) {
        int o = idx >> 5, p = idx & 31;
        out[((size_t)(b * 128 + o)) * NPIX + n0 + p] = sin_[o * 33 + p];
    }
}

// ---------------- launch ----------------
extern "C" void kernel_launch(void* const* d_in, const int* in_sizes, int n_in,
                              void* d_out, int out_size) {
    const float* edge   = (const float*)d_in[0];
    const float* sem    = (const float*)d_in[1];
    const float* fusedf = (const float*)d_in[2];
    const float* b_al   = (const float*)d_in[4];
    const float* b_fal  = (const float*)d_in[6];
    const float* w_q    = (const float*)d_in[7];
    const float* b_q    = (const float*)d_in[8];
    const float* w_k    = (const float*)d_in[9];
    const float* b_k    = (const float*)d_in[10];
    const float* w_f    = (const float*)d_in[11];
    const float* b_f    = (const float*)d_in[12];
    const float* w_al   = (const float*)d_in[3];
    const float* w_fal  = (const float*)d_in[5];
    float* out = (float*)d_out;

    cudaFuncSetAttribute(attn_kernel, cudaFuncAttributeMaxDynamicSharedMemorySize,
                         ATTN_SMEM_BYTES);

    prep_weights_kernel<<<256, 256>>>(w_q, w_k, w_f, w_al, w_fal);
    conv_tile_kernel<<<dim3(16, 4), 256>>>(edge, b_al, 64, 0);
    conv_tile_kernel<<<dim3(16, 4), 256>>>(fusedf, b_fal, 128, 1);
    upsample_sim_kernel<<<dim3(16, 4), 256>>>(sem);
    density_kernel<<<4, 1024>>>();
    vbuild_kernel<<<dim3(128, 8, 4), dim3(32, 8)>>>(sem);
    qk_q_kernel<<<dim3(64, 4), 256>>>(b_q);
    qk_k_kernel<<<dim3(64, 4), 256>>>(sem, b_k);
    attn_kernel<<<dim3(128, 4), 256, ATTN_SMEM_BYTES>>>();
    fusion_kernel<<<dim3(128, 4), 128>>>(b_f, out);
}

// round 4
// speedup vs baseline: 1.1271x; 1.1271x over previous
#include <cuda_runtime.h>

#define BATCH 4
#define NPIX 4096
#define EPS 1e-6f
#define ATTN_SCALE 0.0625f   // 1/sqrt(256)
#define FULLMASK 0xFFFFFFFFu

typedef unsigned long long ull;

// ---------------- scratch (device globals: allocation-free) ----------------
__device__ float g_edge32[BATCH * 128 * 1024];
__device__ float g_fused32[BATCH * 128 * 1024];
__device__ float g_edge_up[BATCH * 128 * NPIX];
__device__ float g_fused_up[BATCH * 128 * NPIX];
__device__ float g_sim[BATCH * NPIX];
__device__ float g_l2e[BATCH * NPIX];
__device__ float g_density[BATCH * NPIX];
__device__ float g_q[BATCH * NPIX * 256];
__device__ float g_k[BATCH * NPIX * 256];
__device__ float g_v[BATCH * NPIX * 256];
__device__ float g_ao[BATCH * NPIX * 256];
__device__ float g_wq2D[128 * 512];   // folded w_q, [c][2o] dup
__device__ float g_wkD[256 * 512];    // w_k [c][2o] dup
__device__ float g_wfD[256 * 256];    // w_fusion [c][2o] dup

// ---------------- f32x2 packed FMA ----------------
__device__ __forceinline__ ull ffma2(ull a, ull b, ull c) {
    ull d;
    asm("fma.rn.f32x2 %0, %1, %2, %3;" : "=l"(d) : "l"(a), "l"(b), "l"(c));
    return d;
}
__device__ __forceinline__ float2 u2f(ull u) {
    union { ull u; float2 f; } t; t.u = u; return t.f;
}
__device__ __forceinline__ ull fdup(float x) {
    union { ull u; float2 f; } t; t.f.x = x; t.f.y = x; return t.u;
}

// ---------------- weight prep: fold/transpose/duplicate ----------------
__global__ void prep_weights_kernel(const float* __restrict__ w_q,
                                    const float* __restrict__ w_k,
                                    const float* __restrict__ w_f) {
    int i = blockIdx.x * 256 + threadIdx.x;   // 0..65535
    int o = i >> 8, c = i & 255;
    float vk = w_k[o * 256 + c];
    g_wkD[c * 512 + 2 * o] = vk;
    g_wkD[c * 512 + 2 * o + 1] = vk;
    if (c < 128) {
        float vq = w_q[o * 256 + c] + w_q[o * 256 + 128 + c];
        g_wq2D[c * 512 + 2 * o] = vq;
        g_wq2D[c * 512 + 2 * o + 1] = vq;
    }
    if (o < 128) {
        float vf = w_f[o * 256 + c];
        g_wfD[c * 256 + 2 * o] = vf;
        g_wfD[c * 256 + 2 * o + 1] = vf;
    }
}

// ---------------- 1x1 conv at 32x32 (massively parallel, R1 style) ----------------
__global__ void conv32_kernel(const float* __restrict__ x,
                              const float* __restrict__ w,
                              const float* __restrict__ bias,
                              int Cin, int which) {
    int p = blockIdx.x * blockDim.x + threadIdx.x;  // 0..1023
    int o = blockIdx.y, b = blockIdx.z;
    const float* xb = x + (size_t)b * Cin * 1024 + p;
    const float* wr = w + o * Cin;
    float acc = bias[o];
    for (int c = 0; c < Cin; c++) acc = fmaf(wr[c], xb[(size_t)c * 1024], acc);
    float* out = which ? g_fused32 : g_edge32;
    out[((size_t)(b * 128 + o)) * 1024 + p] = acc;
}

// ---------------- fused bilinear upsample (32->64) + l2/cosine sim ----------------
// 512 blocks: 32 pixels x 8 channel-parts (16 ch each) per 256-thread block.
__global__ __launch_bounds__(256) void upsample_sim_kernel(const float* __restrict__ sem) {
    __shared__ float rse[8][33], rss[8][33], rdt[8][33];
    int b = blockIdx.y;
    int n0 = blockIdx.x * 32;
    int t = threadIdx.x;
    int p = t & 31, part = t >> 5;
    int n = n0 + p;
    int x = n >> 6, y = n & 63;
    float sx = x * 0.5f - 0.25f;
    int ix = (int)floorf(sx);
    float fx = sx - (float)ix;
    int x0 = min(max(ix, 0), 31), x1 = min(max(ix + 1, 0), 31);
    float sy = y * 0.5f - 0.25f;
    int iy = (int)floorf(sy);
    float fy = sy - (float)iy;
    int y0 = min(max(iy, 0), 31), y1 = min(max(iy + 1, 0), 31);
    float w00 = (1.f - fx) * (1.f - fy), w01 = (1.f - fx) * fy;
    float w10 = fx * (1.f - fy), w11 = fx * fy;
    int i00 = x0 * 32 + y0, i01 = x0 * 32 + y1;
    int i10 = x1 * 32 + y0, i11 = x1 * 32 + y1;
    size_t ib = (size_t)b * 128 * 1024 + (size_t)part * 16 * 1024;
    size_t obase = (size_t)b * 128 * NPIX + (size_t)part * 16 * NPIX + n;
    float se = 0.f, ss = 0.f, dt = 0.f;
#pragma unroll 4
    for (int cl = 0; cl < 16; cl++) {
        const float* e = g_edge32 + ib + (size_t)cl * 1024;
        float ve = w00 * e[i00] + w01 * e[i01] + w10 * e[i10] + w11 * e[i11];
        const float* f = g_fused32 + ib + (size_t)cl * 1024;
        float vf = w00 * f[i00] + w01 * f[i01] + w10 * f[i10] + w11 * f[i11];
        g_edge_up[obase + (size_t)cl * NPIX] = ve;
        g_fused_up[obase + (size_t)cl * NPIX] = vf;
        float s = sem[obase + (size_t)cl * NPIX];
        se = fmaf(ve, ve, se);
        ss = fmaf(s, s, ss);
        dt = fmaf(ve, s, dt);
    }
    rse[part][p] = se;
    rss[part][p] = ss;
    rdt[part][p] = dt;
    __syncthreads();
    if (part == 0) {
        float tse = 0.f, tss = 0.f, tdt = 0.f;
#pragma unroll
        for (int j = 0; j < 8; j++) {
            tse += rse[j][p];
            tss += rss[j][p];
            tdt += rdt[j][p];
        }
        float le = sqrtf(tse), ls = sqrtf(tss);
        g_l2e[b * NPIX + n] = le;
        g_sim[b * NPIX + n] = (tdt / ((le + EPS) * (ls + EPS)) + 1.f) * 0.5f;
    }
}

// ---------------- per-batch softmax over 4096 -> density ----------------
__global__ void density_kernel() {
    int b = blockIdx.x, t = threadIdx.x;
    int lane = t & 31, wid = t >> 5;
    __shared__ float smx[32], ssm[32];
    float v[4];
#pragma unroll
    for (int i = 0; i < 4; i++) v[i] = g_l2e[b * NPIX + t + i * 1024];
    float mx = fmaxf(fmaxf(v[0], v[1]), fmaxf(v[2], v[3]));
#pragma unroll
    for (int off = 16; off; off >>= 1) mx = fmaxf(mx, __shfl_xor_sync(FULLMASK, mx, off));
    if (!lane) smx[wid] = mx;
    __syncthreads();
    if (wid == 0) {
        float m = smx[lane];
#pragma unroll
        for (int off = 16; off; off >>= 1) m = fmaxf(m, __shfl_xor_sync(FULLMASK, m, off));
        smx[lane] = m;
    }
    __syncthreads();
    mx = smx[0];
    float e[4], s = 0.f;
#pragma unroll
    for (int i = 0; i < 4; i++) { e[i] = expf(v[i] - mx); s += e[i]; }
#pragma unroll
    for (int off = 16; off; off >>= 1) s += __shfl_xor_sync(FULLMASK, s, off);
    if (!lane) ssm[wid] = s;
    __syncthreads();
    if (wid == 0) {
        float x = ssm[lane];
#pragma unroll
        for (int off = 16; off; off >>= 1) x += __shfl_xor_sync(FULLMASK, x, off);
        ssm[lane] = x;
    }
    __syncthreads();
    float sc = 4096.f / ssm[0];
#pragma unroll
    for (int i = 0; i < 4; i++) g_density[b * NPIX + t + i * 1024] = e[i] * sc;
}

// ---------------- build V = concat(sem_raw, fused) pixel-major ----------------
__global__ void vbuild_kernel(const float* __restrict__ sem) {
    __shared__ float tile[32][33];
    int b = blockIdx.z;
    int n0 = blockIdx.x * 32;
    int cb = blockIdx.y;  // 0..7 (0-3: sem, 4-7: fused)
    int c0 = cb * 32;
    const float* src = (cb < 4) ? (sem + ((size_t)b * 128 + c0) * NPIX)
                                : (g_fused_up + ((size_t)b * 128 + (c0 - 128)) * NPIX);
    int tx = threadIdx.x, ty = threadIdx.y;
    for (int i = ty; i < 32; i += 8)
        tile[i][tx] = src[(size_t)i * NPIX + n0 + tx];
    __syncthreads();
    for (int i = ty; i < 32; i += 8)
        g_v[((size_t)b * NPIX + n0 + i) * 256 + c0 + tx] = tile[tx][i];
}

// ---------------- q projection: 64 pixels/block GEMM ----------------
__global__ __launch_bounds__(256, 2) void qk_q_kernel(const float* __restrict__ b_q) {
    __shared__ float sq[128 * 64];
    int b = blockIdx.y, n0 = blockIdx.x * 64, t = threadIdx.x;
#pragma unroll
    for (int it = 0; it < 32; it++) {
        int idx = it * 256 + t;
        int c = idx >> 6, nl = idx & 63;
        int n = n0 + nl;
        sq[idx] = g_edge_up[(size_t)(b * 128 + c) * NPIX + n] * g_sim[b * NPIX + n];
    }
    __syncthreads();
    ull acc[32];
    ull bq = fdup(b_q[t]);
#pragma unroll
    for (int j = 0; j < 32; j++) acc[j] = bq;
#pragma unroll 2
    for (int c = 0; c < 128; c++) {
        ull w = *(const ull*)&g_wq2D[c * 512 + 2 * t];
        const ulonglong2* row = (const ulonglong2*)&sq[c * 64];
#pragma unroll
        for (int j = 0; j < 16; j++) {
            ulonglong2 v = row[j];
            acc[2 * j] = ffma2(w, v.x, acc[2 * j]);
            acc[2 * j + 1] = ffma2(w, v.y, acc[2 * j + 1]);
        }
    }
    size_t ob = ((size_t)b * NPIX + n0) * 256 + t;
#pragma unroll
    for (int j = 0; j < 32; j++) {
        float2 f = u2f(acc[j]);
        g_q[ob + (size_t)(2 * j) * 256] = f.x;
        g_q[ob + (size_t)(2 * j + 1) * 256] = f.y;
    }
}

// ---------------- k projection: 64 pixels/block GEMM, c chunked ----------------
__global__ __launch_bounds__(256, 2) void qk_k_kernel(const float* __restrict__ sem,
                                                      const float* __restrict__ b_k) {
    __shared__ float sk[64 * 64];
    int b = blockIdx.y, n0 = blockIdx.x * 64, t = threadIdx.x;
    ull acc[32];
    ull bk = fdup(b_k[t]);
#pragma unroll
    for (int j = 0; j < 32; j++) acc[j] = bk;
    for (int cc = 0; cc < 4; cc++) {
        __syncthreads();
#pragma unroll
        for (int it = 0; it < 16; it++) {
            int idx = it * 256 + t;
            int c = idx >> 6, nl = idx & 63;
            int cg = cc * 64 + c;
            int n = n0 + nl;
            float v;
            if (cg < 128)
                v = sem[(size_t)(b * 128 + cg) * NPIX + n] * g_density[b * NPIX + n];
            else
                v = g_fused_up[(size_t)(b * 128 + cg - 128) * NPIX + n];
            sk[idx] = v;
        }
        __syncthreads();
#pragma unroll 2
        for (int c = 0; c < 64; c++) {
            ull w = *(const ull*)&g_wkD[(cc * 64 + c) * 512 + 2 * t];
            const ulonglong2* row = (const ulonglong2*)&sk[c * 64];
#pragma unroll
            for (int j = 0; j < 16; j++) {
                ulonglong2 v = row[j];
                acc[2 * j] = ffma2(w, v.x, acc[2 * j]);
                acc[2 * j + 1] = ffma2(w, v.y, acc[2 * j + 1]);
            }
        }
    }
    size_t ob = ((size_t)b * NPIX + n0) * 256 + t;
#pragma unroll
    for (int j = 0; j < 32; j++) {
        float2 f = u2f(acc[j]);
        g_k[ob + (size_t)(2 * j) * 256] = f.x;
        g_k[ob + (size_t)(2 * j + 1) * 256] = f.y;
    }
}

// ---------------- local windowed attention ----------------
// Query tile 8(x) x 4(y) = 32 q. Key window 18(x) x 14(y) = 252, padded to 256.
#define KV_F 8192                // 32 x 256
#define PS_STRIDE 66
#define PS_F (256 * PS_STRIDE)
#define QS_STRIDE 68
#define QS_F (32 * QS_STRIDE)
#define RED_F 288
#define ATTN_SMEM_BYTES ((KV_F + PS_F + QS_F + RED_F) * 4)

__global__ __launch_bounds__(256, 2) void attn_kernel() {
    extern __shared__ float sm[];
    float* KV = sm;
    float* Ps = sm + KV_F;
    float* Qs = sm + KV_F + PS_F;
    float* red = sm + KV_F + PS_F + QS_F;

    int t = threadIdx.x, b = blockIdx.y, tile = blockIdx.x;
    int qx0 = (tile >> 4) * 8, qy0 = (tile & 15) * 4;
    int warp = t >> 5, lane = t & 31;
    int qg = lane & 3, kgl = lane >> 2;
    int kg = warp * 8 + kgl;
    size_t kvbase = (size_t)b * NPIX * 256;

    // ---- QK ----
    ull accl[8][2];
#pragma unroll
    for (int qi = 0; qi < 8; qi++) { accl[qi][0] = 0ull; accl[qi][1] = 0ull; }

    for (int cc = 0; cc < 8; cc++) {
        __syncthreads();
        {
            int ki = t;
            int kr = ki / 14, kc = ki - 14 * kr;
            int kx = min(max(qx0 - 5 + kr, 0), 63);
            int ky = min(max(qy0 - 5 + kc, 0), 63);
            const float* src = &g_k[kvbase + (size_t)((kx << 6) + ky) * 256 + cc * 32];
#pragma unroll
            for (int c4 = 0; c4 < 8; c4++) {
                float4 v = *(const float4*)(src + c4 * 4);
                KV[(c4 * 4 + 0) * 256 + ki] = v.x;
                KV[(c4 * 4 + 1) * 256 + ki] = v.y;
                KV[(c4 * 4 + 2) * 256 + ki] = v.z;
                KV[(c4 * 4 + 3) * 256 + ki] = v.w;
            }
        }
#pragma unroll
        for (int it = 0; it < 4; it++) {
            int idx = it * 256 + t;
            int q = idx >> 5, c = idx & 31;
            int nq = ((qx0 + (q >> 2)) << 6) + qy0 + (q & 3);
            float qv = g_q[kvbase + (size_t)nq * 256 + cc * 32 + c] * ATTN_SCALE;
            Qs[c * QS_STRIDE + 2 * q] = qv;
            Qs[c * QS_STRIDE + 2 * q + 1] = qv;
        }
        __syncthreads();
#pragma unroll 4
        for (int c = 0; c < 32; c++) {
            ulonglong2 kk = *(const ulonglong2*)&KV[c * 256 + kg * 4];
            const float* qrow = &Qs[c * QS_STRIDE];
#pragma unroll
            for (int qi = 0; qi < 8; qi++) {
                ull qd = *(const ull*)&qrow[2 * (qi * 4 + qg)];
                accl[qi][0] = ffma2(qd, kk.x, accl[qi][0]);
                accl[qi][1] = ffma2(qd, kk.y, accl[qi][1]);
            }
        }
    }

    // ---- unpack + mask ----
    float lg[8][4];
    int krA[4];
    bool bok[4];
#pragma unroll
    for (int kj = 0; kj < 4; kj++) {
        int ki = kg * 4 + kj;
        int kr = ki / 14, kc = ki - 14 * kr;
        int kx = qx0 - 5 + kr, ky = qy0 - 5 + kc;
        krA[kj] = kr;
        bok[kj] = (ki < 252) && (kx >= 0) && (kx < 64) && (ky >= 0) && (ky < 64)
                  && (kc >= qg) && (kc <= qg + 10);
    }
#pragma unroll
    for (int qi = 0; qi < 8; qi++) {
        float2 a = u2f(accl[qi][0]), bb = u2f(accl[qi][1]);
        lg[qi][0] = a.x; lg[qi][1] = a.y; lg[qi][2] = bb.x; lg[qi][3] = bb.y;
#pragma unroll
        for (int kj = 0; kj < 4; kj++) {
            bool ok = bok[kj] && (krA[kj] >= qi) && (krA[kj] <= qi + 10);
            if (!ok) lg[qi][kj] = -1e30f;
        }
    }

    // ---- softmax ----
    float mx[8];
#pragma unroll
    for (int qi = 0; qi < 8; qi++) {
        float m = fmaxf(fmaxf(lg[qi][0], lg[qi][1]), fmaxf(lg[qi][2], lg[qi][3]));
        m = fmaxf(m, __shfl_xor_sync(FULLMASK, m, 4));
        m = fmaxf(m, __shfl_xor_sync(FULLMASK, m, 8));
        m = fmaxf(m, __shfl_xor_sync(FULLMASK, m, 16));
        if (kgl == 0) red[(qi * 4 + qg) * 8 + warp] = m;
    }
    __syncthreads();
#pragma unroll
    for (int qi = 0; qi < 8; qi++) {
        float m = -1e30f;
#pragma unroll
        for (int w = 0; w < 8; w++) m = fmaxf(m, red[(qi * 4 + qg) * 8 + w]);
        mx[qi] = m;
    }
    __syncthreads();
    float pv[8][4];
#pragma unroll
    for (int qi = 0; qi < 8; qi++) {
        float s = 0.f;
#pragma unroll
        for (int kj = 0; kj < 4; kj++) {
            pv[qi][kj] = __expf(lg[qi][kj] - mx[qi]);
            s += pv[qi][kj];
        }
        s += __shfl_xor_sync(FULLMASK, s, 4);
        s += __shfl_xor_sync(FULLMASK, s, 8);
        s += __shfl_xor_sync(FULLMASK, s, 16);
        if (kgl == 0) red[(qi * 4 + qg) * 8 + warp] = s;
    }
    __syncthreads();
#pragma unroll
    for (int qi = 0; qi < 8; qi++) {
        float s = 0.f;
#pragma unroll
        for (int w = 0; w < 8; w++) s += red[(qi * 4 + qg) * 8 + w];
        float inv = 1.f / s;
#pragma unroll
        for (int kj = 0; kj < 4; kj++) {
            float p = pv[qi][kj] * inv;
            float* dst = &Ps[(kg * 4 + kj) * PS_STRIDE + 2 * (qi * 4 + qg)];
            dst[0] = p;
            dst[1] = p;
        }
    }

    // ---- AV ----
    ull acco[8][2];
#pragma unroll
    for (int qi = 0; qi < 8; qi++) { acco[qi][0] = 0ull; acco[qi][1] = 0ull; }

    for (int kc4 = 0; kc4 < 8; kc4++) {
        __syncthreads();
#pragma unroll
        for (int it = 0; it < 8; it++) {
            int idx = it * 256 + t;
            int kil = idx >> 6, cg = idx & 63;
            int ki = kc4 * 32 + kil;
            int kr = ki / 14, kc = ki - 14 * kr;
            int kx = min(max(qx0 - 5 + kr, 0), 63);
            int ky = min(max(qy0 - 5 + kc, 0), 63);
            *(float4*)&KV[kil * 256 + cg * 4] =
                *(const float4*)&g_v[kvbase + (size_t)((kx << 6) + ky) * 256 + cg * 4];
        }
        __syncthreads();
#pragma unroll 4
        for (int kil = 0; kil < 32; kil++) {
            ulonglong2 vv = *(const ulonglong2*)&KV[kil * 256 + kg * 4];
            const float* prow = &Ps[(kc4 * 32 + kil) * PS_STRIDE];
#pragma unroll
            for (int qi = 0; qi < 8; qi++) {
                ull pd = *(const ull*)&prow[2 * (qi * 4 + qg)];
                acco[qi][0] = ffma2(pd, vv.x, acco[qi][0]);
                acco[qi][1] = ffma2(pd, vv.y, acco[qi][1]);
            }
        }
    }

#pragma unroll
    for (int qi = 0; qi < 8; qi++) {
        int nq = ((qx0 + qi) << 6) + qy0 + qg;
        ull* dst = (ull*)&g_ao[kvbase + (size_t)nq * 256 + kg * 4];
        dst[0] = acco[qi][0];
        dst[1] = acco[qi][1];
    }
}

// ---------------- fusion 1x1 conv -> d_out [b,128,64,64] ----------------
__global__ __launch_bounds__(128) void fusion_kernel(const float* __restrict__ b_f,
                                                     float* __restrict__ out) {
    __shared__ float sin_[256 * 36];
    int b = blockIdx.y, n0 = blockIdx.x * 32, tid = threadIdx.x;
    for (int idx = tid; idx < 32 * 256; idx += 128) {
        int p = idx >> 8, c = idx & 255;
        sin_[c * 36 + p] = g_ao[((size_t)b * NPIX + n0 + p) * 256 + c];
    }
    __syncthreads();
    ull acc[16];
    ull bo = fdup(b_f[tid]);
#pragma unroll
    for (int j = 0; j < 16; j++) acc[j] = bo;
#pragma unroll 4
    for (int c = 0; c < 256; c++) {
        ull w = *(const ull*)&g_wfD[c * 256 + 2 * tid];
        const float* row = &sin_[c * 36];
#pragma unroll
        for (int j = 0; j < 8; j++) {
            ulonglong2 v = *(const ulonglong2*)&row[j * 4];
            acc[2 * j] = ffma2(w, v.x, acc[2 * j]);
            acc[2 * j + 1] = ffma2(w, v.y, acc[2 * j + 1]);
        }
    }
    __syncthreads();
#pragma unroll
    for (int j = 0; j < 16; j++) {
        float2 f = u2f(acc[j]);
        sin_[tid * 33 + 2 * j] = f.x;
        sin_[tid * 33 + 2 * j + 1] = f.y;
    }
    __syncthreads();
    for (int idx = tid; idx < 128 * 32; idx += 128) {
        int o = idx >> 5, p = idx & 31;
        out[((size_t)(b * 128 + o)) * NPIX + n0 + p] = sin_[o * 33 + p];
    }
}

// ---------------- launch ----------------
extern "C" void kernel_launch(void* const* d_in, const int* in_sizes, int n_in,
                              void* d_out, int out_size) {
    const float* edge   = (const float*)d_in[0];
    const float* sem    = (const float*)d_in[1];
    const float* fusedf = (const float*)d_in[2];
    const float* w_al   = (const float*)d_in[3];
    const float* b_al   = (const float*)d_in[4];
    const float* w_fal  = (const float*)d_in[5];
    const float* b_fal  = (const float*)d_in[6];
    const float* w_q    = (const float*)d_in[7];
    const float* b_q    = (const float*)d_in[8];
    const float* w_k    = (const float*)d_in[9];
    const float* b_k    = (const float*)d_in[10];
    const float* w_f    = (const float*)d_in[11];
    const float* b_f    = (const float*)d_in[12];
    float* out = (float*)d_out;

    cudaFuncSetAttribute(attn_kernel, cudaFuncAttributeMaxDynamicSharedMemorySize,
                         ATTN_SMEM_BYTES);

    prep_weights_kernel<<<256, 256>>>(w_q, w_k, w_f);
    conv32_kernel<<<dim3(4, 128, 4), 256>>>(edge, w_al, b_al, 64, 0);
    conv32_kernel<<<dim3(4, 128, 4), 256>>>(fusedf, w_fal, b_fal, 128, 1);
    upsample_sim_kernel<<<dim3(128, 4), 256>>>(sem);
    density_kernel<<<4, 1024>>>();
    vbuild_kernel<<<dim3(128, 8, 4), dim3(32, 8)>>>(sem);
    qk_q_kernel<<<dim3(64, 4), 256>>>(b_q);
    qk_k_kernel<<<dim3(64, 4), 256>>>(sem, b_k);
    attn_kernel<<<dim3(128, 4), 256, ATTN_SMEM_BYTES>>>();
    fusion_kernel<<<dim3(128, 4), 128>>>(b_f, out);
}

// round 5
// speedup vs baseline: 1.2395x; 1.0997x over previous
#include <cuda_runtime.h>

#define BATCH 4
#define NPIX 4096
#define EPS 1e-6f
#define ATTN_SCALE 0.0625f   // 1/sqrt(256)
#define FULLMASK 0xFFFFFFFFu

typedef unsigned long long ull;

// ---------------- scratch (device globals: allocation-free) ----------------
__device__ float g_edge32[BATCH * 128 * 1024];
__device__ float g_fused32[BATCH * 128 * 1024];
__device__ float g_edge_up[BATCH * 128 * NPIX];
__device__ float g_fused_up[BATCH * 128 * NPIX];
__device__ float g_sim[BATCH * NPIX];
__device__ float g_l2e[BATCH * NPIX];
__device__ float g_density[BATCH * NPIX];
__device__ float g_q[BATCH * NPIX * 256];
__device__ float g_k[BATCH * NPIX * 256];
__device__ float g_v[BATCH * NPIX * 256];
__device__ float g_ao[BATCH * NPIX * 256];
__device__ float g_wq2D[128 * 512];   // folded w_q, [c][2o] dup
__device__ float g_wkD[256 * 512];    // w_k [c][2o] dup
__device__ float g_wfD[256 * 256];    // w_fusion [c][2o] dup

// ---------------- f32x2 packed FMA ----------------
__device__ __forceinline__ ull ffma2(ull a, ull b, ull c) {
    ull d;
    asm("fma.rn.f32x2 %0, %1, %2, %3;" : "=l"(d) : "l"(a), "l"(b), "l"(c));
    return d;
}
__device__ __forceinline__ float2 u2f(ull u) {
    union { ull u; float2 f; } t; t.u = u; return t.f;
}
__device__ __forceinline__ ull fdup(float x) {
    union { ull u; float2 f; } t; t.f.x = x; t.f.y = x; return t.u;
}

// =====================================================================
// L1: weight prep + both 1x1 convs at 32x32, fused into one launch
// blocks [0,256): prep;  [256, 256+2048): conv (2 tensors x 4 b x 128 o x 2 halves)
// =====================================================================
__global__ __launch_bounds__(256) void prep_conv_kernel(
        const float* __restrict__ w_q, const float* __restrict__ w_k,
        const float* __restrict__ w_f,
        const float* __restrict__ edge, const float* __restrict__ fusedf,
        const float* __restrict__ w_al, const float* __restrict__ b_al,
        const float* __restrict__ w_fal, const float* __restrict__ b_fal) {
    int bx = blockIdx.x, t = threadIdx.x;
    if (bx < 256) {
        int i = bx * 256 + t;
        int o = i >> 8, c = i & 255;
        float vk = w_k[o * 256 + c];
        g_wkD[c * 512 + 2 * o] = vk;
        g_wkD[c * 512 + 2 * o + 1] = vk;
        if (c < 128) {
            float vq = w_q[o * 256 + c] + w_q[o * 256 + 128 + c];
            g_wq2D[c * 512 + 2 * o] = vq;
            g_wq2D[c * 512 + 2 * o + 1] = vq;
        }
        if (o < 128) {
            float vf = w_f[o * 256 + c];
            g_wfD[c * 256 + 2 * o] = vf;
            g_wfD[c * 256 + 2 * o + 1] = vf;
        }
        return;
    }
    int e = bx - 256;
    int which = e >> 10, r = e & 1023;
    int b = r >> 8, o = (r >> 1) & 127, half = r & 1;
    int Cin = which ? 128 : 64;
    const float* x = which ? fusedf : edge;
    const float* w = which ? w_fal : w_al;
    float bias = which ? b_fal[o] : b_al[o];
    int p0 = half * 512 + t * 2;
    const float* xb = x + (size_t)b * Cin * 1024 + p0;
    const float* wr = w + o * Cin;
    ull acc = fdup(bias);
    for (int c = 0; c < Cin; c++) {
        ull xv = *(const ull*)&xb[(size_t)c * 1024];
        acc = ffma2(fdup(wr[c]), xv, acc);
    }
    float* out = which ? g_fused32 : g_edge32;
    *(ull*)&out[((size_t)(b * 128 + o)) * 1024 + p0] = acc;
}

// =====================================================================
// L2: fused bilinear upsample (32->64) + l2/cosine sim
// 512 blocks: 32 pixels x 8 channel-parts (16 ch each)
// =====================================================================
__global__ __launch_bounds__(256) void upsample_sim_kernel(const float* __restrict__ sem) {
    __shared__ float rse[8][33], rss[8][33], rdt[8][33];
    int b = blockIdx.y;
    int n0 = blockIdx.x * 32;
    int t = threadIdx.x;
    int p = t & 31, part = t >> 5;
    int n = n0 + p;
    int x = n >> 6, y = n & 63;
    float sx = x * 0.5f - 0.25f;
    int ix = (int)floorf(sx);
    float fx = sx - (float)ix;
    int x0 = min(max(ix, 0), 31), x1 = min(max(ix + 1, 0), 31);
    float sy = y * 0.5f - 0.25f;
    int iy = (int)floorf(sy);
    float fy = sy - (float)iy;
    int y0 = min(max(iy, 0), 31), y1 = min(max(iy + 1, 0), 31);
    float w00 = (1.f - fx) * (1.f - fy), w01 = (1.f - fx) * fy;
    float w10 = fx * (1.f - fy), w11 = fx * fy;
    int i00 = x0 * 32 + y0, i01 = x0 * 32 + y1;
    int i10 = x1 * 32 + y0, i11 = x1 * 32 + y1;
    size_t ib = (size_t)b * 128 * 1024 + (size_t)part * 16 * 1024;
    size_t obase = (size_t)b * 128 * NPIX + (size_t)part * 16 * NPIX + n;
    float se = 0.f, ss = 0.f, dt = 0.f;
#pragma unroll 4
    for (int cl = 0; cl < 16; cl++) {
        const float* e = g_edge32 + ib + (size_t)cl * 1024;
        float ve = w00 * e[i00] + w01 * e[i01] + w10 * e[i10] + w11 * e[i11];
        const float* f = g_fused32 + ib + (size_t)cl * 1024;
        float vf = w00 * f[i00] + w01 * f[i01] + w10 * f[i10] + w11 * f[i11];
        g_edge_up[obase + (size_t)cl * NPIX] = ve;
        g_fused_up[obase + (size_t)cl * NPIX] = vf;
        float s = sem[obase + (size_t)cl * NPIX];
        se = fmaf(ve, ve, se);
        ss = fmaf(s, s, ss);
        dt = fmaf(ve, s, dt);
    }
    rse[part][p] = se;
    rss[part][p] = ss;
    rdt[part][p] = dt;
    __syncthreads();
    if (part == 0) {
        float tse = 0.f, tss = 0.f, tdt = 0.f;
#pragma unroll
        for (int j = 0; j < 8; j++) {
            tse += rse[j][p];
            tss += rss[j][p];
            tdt += rdt[j][p];
        }
        float le = sqrtf(tse), ls = sqrtf(tss);
        g_l2e[b * NPIX + n] = le;
        g_sim[b * NPIX + n] = (tdt / ((le + EPS) * (ls + EPS)) + 1.f) * 0.5f;
    }
}

// =====================================================================
// L3: qk_q (512 blocks) + vbuild (4096 blocks) + density (4 blocks)
// =====================================================================
__global__ __launch_bounds__(256) void mid_kernel(const float* __restrict__ sem,
                                                  const float* __restrict__ b_q) {
    __shared__ float sbuf[4096];
    int bx = blockIdx.x, t = threadIdx.x;

    if (bx < 512) {
        // ---- qk_q: 32 px, 2 outputs per thread ----
        int b = bx >> 7, n0 = (bx & 127) * 32;
#pragma unroll
        for (int it = 0; it < 16; it++) {
            int idx = it * 256 + t;
            int c = idx >> 5, p = idx & 31;
            int n = n0 + p;
            sbuf[idx] = g_edge_up[(size_t)(b * 128 + c) * NPIX + n] * g_sim[b * NPIX + n];
        }
        __syncthreads();
        int oo = t & 127, ph = t >> 7;
        ull acc[2][8];
        ull b0 = fdup(b_q[oo]), b1 = fdup(b_q[oo + 128]);
#pragma unroll
        for (int j = 0; j < 8; j++) { acc[0][j] = b0; acc[1][j] = b1; }
#pragma unroll 4
        for (int c = 0; c < 128; c++) {
            ull w0 = *(const ull*)&g_wq2D[c * 512 + 2 * oo];
            ull w1 = *(const ull*)&g_wq2D[c * 512 + 2 * oo + 256];
            const ulonglong2* row = (const ulonglong2*)&sbuf[c * 32 + ph * 16];
#pragma unroll
            for (int j = 0; j < 4; j++) {
                ulonglong2 v = row[j];
                acc[0][2 * j] = ffma2(w0, v.x, acc[0][2 * j]);
                acc[0][2 * j + 1] = ffma2(w0, v.y, acc[0][2 * j + 1]);
                acc[1][2 * j] = ffma2(w1, v.x, acc[1][2 * j]);
                acc[1][2 * j + 1] = ffma2(w1, v.y, acc[1][2 * j + 1]);
            }
        }
        size_t ob = ((size_t)b * NPIX + n0 + ph * 16) * 256 + oo;
#pragma unroll
        for (int h = 0; h < 2; h++)
#pragma unroll
            for (int j = 0; j < 8; j++) {
                float2 f = u2f(acc[h][j]);
                g_q[ob + (size_t)(2 * j) * 256 + h * 128] = f.x;
                g_q[ob + (size_t)(2 * j + 1) * 256 + h * 128] = f.y;
            }
        return;
    }
    if (bx < 512 + 4096) {
        // ---- vbuild: transpose into pixel-major V ----
        int idx = bx - 512;
        int n0 = (idx & 127) * 32;
        int cb = (idx >> 7) & 7;
        int b = idx >> 10;
        int c0 = cb * 32;
        const float* src = (cb < 4) ? (sem + ((size_t)b * 128 + c0) * NPIX)
                                    : (g_fused_up + ((size_t)b * 128 + (c0 - 128)) * NPIX);
        float (*tile)[33] = (float(*)[33])sbuf;
        int tx = t & 31, ty = t >> 5;
#pragma unroll
        for (int i = ty; i < 32; i += 8)
            tile[i][tx] = src[(size_t)i * NPIX + n0 + tx];
        __syncthreads();
#pragma unroll
        for (int i = ty; i < 32; i += 8)
            g_v[((size_t)b * NPIX + n0 + i) * 256 + c0 + tx] = tile[tx][i];
        return;
    }
    // ---- density: per-batch softmax over 4096 ----
    int b = bx - (512 + 4096);
    int lane = t & 31, wid = t >> 5;
    float v[16];
#pragma unroll
    for (int i = 0; i < 16; i++) v[i] = g_l2e[b * NPIX + t + i * 256];
    float mx = v[0];
#pragma unroll
    for (int i = 1; i < 16; i++) mx = fmaxf(mx, v[i]);
#pragma unroll
    for (int off = 16; off; off >>= 1) mx = fmaxf(mx, __shfl_xor_sync(FULLMASK, mx, off));
    if (!lane) sbuf[wid] = mx;
    __syncthreads();
    mx = sbuf[0];
#pragma unroll
    for (int w = 1; w < 8; w++) mx = fmaxf(mx, sbuf[w]);
    float e[16], s = 0.f;
#pragma unroll
    for (int i = 0; i < 16; i++) { e[i] = expf(v[i] - mx); s += e[i]; }
#pragma unroll
    for (int off = 16; off; off >>= 1) s += __shfl_xor_sync(FULLMASK, s, off);
    __syncthreads();
    if (!lane) sbuf[8 + wid] = s;
    __syncthreads();
    s = 0.f;
#pragma unroll
    for (int w = 0; w < 8; w++) s += sbuf[8 + w];
    float sc = 4096.f / s;
#pragma unroll
    for (int i = 0; i < 16; i++) g_density[b * NPIX + t + i * 256] = e[i] * sc;
}

// =====================================================================
// L4: k projection — 32 px/block, 2 outputs/thread, c chunked (PROFILE SLOT)
// =====================================================================
__global__ __launch_bounds__(256) void qk_k_kernel(const float* __restrict__ sem,
                                                   const float* __restrict__ b_k) {
    __shared__ float sk[64 * 32];
    int b = blockIdx.y, n0 = blockIdx.x * 32, t = threadIdx.x;
    int oo = t & 127, ph = t >> 7;
    ull acc[2][8];
    ull b0 = fdup(b_k[oo]), b1 = fdup(b_k[oo + 128]);
#pragma unroll
    for (int j = 0; j < 8; j++) { acc[0][j] = b0; acc[1][j] = b1; }
    for (int cc = 0; cc < 4; cc++) {
        __syncthreads();
#pragma unroll
        for (int it = 0; it < 8; it++) {
            int idx = it * 256 + t;
            int c = idx >> 5, p = idx & 31;
            int cg = cc * 64 + c;
            int n = n0 + p;
            float v;
            if (cg < 128)
                v = sem[(size_t)(b * 128 + cg) * NPIX + n] * g_density[b * NPIX + n];
            else
                v = g_fused_up[(size_t)(b * 128 + cg - 128) * NPIX + n];
            sk[idx] = v;
        }
        __syncthreads();
#pragma unroll 4
        for (int c = 0; c < 64; c++) {
            ull w0 = *(const ull*)&g_wkD[(cc * 64 + c) * 512 + 2 * oo];
            ull w1 = *(const ull*)&g_wkD[(cc * 64 + c) * 512 + 2 * oo + 256];
            const ulonglong2* row = (const ulonglong2*)&sk[c * 32 + ph * 16];
#pragma unroll
            for (int j = 0; j < 4; j++) {
                ulonglong2 v = row[j];
                acc[0][2 * j] = ffma2(w0, v.x, acc[0][2 * j]);
                acc[0][2 * j + 1] = ffma2(w0, v.y, acc[0][2 * j + 1]);
                acc[1][2 * j] = ffma2(w1, v.x, acc[1][2 * j]);
                acc[1][2 * j + 1] = ffma2(w1, v.y, acc[1][2 * j + 1]);
            }
        }
    }
    size_t ob = ((size_t)b * NPIX + n0 + ph * 16) * 256 + oo;
#pragma unroll
    for (int h = 0; h < 2; h++)
#pragma unroll
        for (int j = 0; j < 8; j++) {
            float2 f = u2f(acc[h][j]);
            g_k[ob + (size_t)(2 * j) * 256 + h * 128] = f.x;
            g_k[ob + (size_t)(2 * j + 1) * 256 + h * 128] = f.y;
        }
}

// =====================================================================
// L5: local windowed attention (identical to R4)
// =====================================================================
#define KV_F 8192
#define PS_STRIDE 66
#define PS_F (256 * PS_STRIDE)
#define QS_STRIDE 68
#define QS_F (32 * QS_STRIDE)
#define RED_F 288
#define ATTN_SMEM_BYTES ((KV_F + PS_F + QS_F + RED_F) * 4)

__global__ __launch_bounds__(256, 2) void attn_kernel() {
    extern __shared__ float sm[];
    float* KV = sm;
    float* Ps = sm + KV_F;
    float* Qs = sm + KV_F + PS_F;
    float* red = sm + KV_F + PS_F + QS_F;

    int t = threadIdx.x, b = blockIdx.y, tile = blockIdx.x;
    int qx0 = (tile >> 4) * 8, qy0 = (tile & 15) * 4;
    int warp = t >> 5, lane = t & 31;
    int qg = lane & 3, kgl = lane >> 2;
    int kg = warp * 8 + kgl;
    size_t kvbase = (size_t)b * NPIX * 256;

    ull accl[8][2];
#pragma unroll
    for (int qi = 0; qi < 8; qi++) { accl[qi][0] = 0ull; accl[qi][1] = 0ull; }

    for (int cc = 0; cc < 8; cc++) {
        __syncthreads();
        {
            int ki = t;
            int kr = ki / 14, kc = ki - 14 * kr;
            int kx = min(max(qx0 - 5 + kr, 0), 63);
            int ky = min(max(qy0 - 5 + kc, 0), 63);
            const float* src = &g_k[kvbase + (size_t)((kx << 6) + ky) * 256 + cc * 32];
#pragma unroll
            for (int c4 = 0; c4 < 8; c4++) {
                float4 v = *(const float4*)(src + c4 * 4);
                KV[(c4 * 4 + 0) * 256 + ki] = v.x;
                KV[(c4 * 4 + 1) * 256 + ki] = v.y;
                KV[(c4 * 4 + 2) * 256 + ki] = v.z;
                KV[(c4 * 4 + 3) * 256 + ki] = v.w;
            }
        }
#pragma unroll
        for (int it = 0; it < 4; it++) {
            int idx = it * 256 + t;
            int q = idx >> 5, c = idx & 31;
            int nq = ((qx0 + (q >> 2)) << 6) + qy0 + (q & 3);
            float qv = g_q[kvbase + (size_t)nq * 256 + cc * 32 + c] * ATTN_SCALE;
            Qs[c * QS_STRIDE + 2 * q] = qv;
            Qs[c * QS_STRIDE + 2 * q + 1] = qv;
        }
        __syncthreads();
#pragma unroll 4
        for (int c = 0; c < 32; c++) {
            ulonglong2 kk = *(const ulonglong2*)&KV[c * 256 + kg * 4];
            const float* qrow = &Qs[c * QS_STRIDE];
#pragma unroll
            for (int qi = 0; qi < 8; qi++) {
                ull qd = *(const ull*)&qrow[2 * (qi * 4 + qg)];
                accl[qi][0] = ffma2(qd, kk.x, accl[qi][0]);
                accl[qi][1] = ffma2(qd, kk.y, accl[qi][1]);
            }
        }
    }

    float lg[8][4];
    int krA[4];
    bool bok[4];
#pragma unroll
    for (int kj = 0; kj < 4; kj++) {
        int ki = kg * 4 + kj;
        int kr = ki / 14, kc = ki - 14 * kr;
        int kx = qx0 - 5 + kr, ky = qy0 - 5 + kc;
        krA[kj] = kr;
        bok[kj] = (ki < 252) && (kx >= 0) && (kx < 64) && (ky >= 0) && (ky < 64)
                  && (kc >= qg) && (kc <= qg + 10);
    }
#pragma unroll
    for (int qi = 0; qi < 8; qi++) {
        float2 a = u2f(accl[qi][0]), bb = u2f(accl[qi][1]);
        lg[qi][0] = a.x; lg[qi][1] = a.y; lg[qi][2] = bb.x; lg[qi][3] = bb.y;
#pragma unroll
        for (int kj = 0; kj < 4; kj++) {
            bool ok = bok[kj] && (krA[kj] >= qi) && (krA[kj] <= qi + 10);
            if (!ok) lg[qi][kj] = -1e30f;
        }
    }

    float mx[8];
#pragma unroll
    for (int qi = 0; qi < 8; qi++) {
        float m = fmaxf(fmaxf(lg[qi][0], lg[qi][1]), fmaxf(lg[qi][2], lg[qi][3]));
        m = fmaxf(m, __shfl_xor_sync(FULLMASK, m, 4));
        m = fmaxf(m, __shfl_xor_sync(FULLMASK, m, 8));
        m = fmaxf(m, __shfl_xor_sync(FULLMASK, m, 16));
        if (kgl == 0) red[(qi * 4 + qg) * 8 + warp] = m;
    }
    __syncthreads();
#pragma unroll
    for (int qi = 0; qi < 8; qi++) {
        float m = -1e30f;
#pragma unroll
        for (int w = 0; w < 8; w++) m = fmaxf(m, red[(qi * 4 + qg) * 8 + w]);
        mx[qi] = m;
    }
    __syncthreads();
    float pv[8][4];
#pragma unroll
    for (int qi = 0; qi < 8; qi++) {
        float s = 0.f;
#pragma unroll
        for (int kj = 0; kj < 4; kj++) {
            pv[qi][kj] = __expf(lg[qi][kj] - mx[qi]);
            s += pv[qi][kj];
        }
        s += __shfl_xor_sync(FULLMASK, s, 4);
        s += __shfl_xor_sync(FULLMASK, s, 8);
        s += __shfl_xor_sync(FULLMASK, s, 16);
        if (kgl == 0) red[(qi * 4 + qg) * 8 + warp] = s;
    }
    __syncthreads();
#pragma unroll
    for (int qi = 0; qi < 8; qi++) {
        float s = 0.f;
#pragma unroll
        for (int w = 0; w < 8; w++) s += red[(qi * 4 + qg) * 8 + w];
        float inv = 1.f / s;
#pragma unroll
        for (int kj = 0; kj < 4; kj++) {
            float p = pv[qi][kj] * inv;
            float* dst = &Ps[(kg * 4 + kj) * PS_STRIDE + 2 * (qi * 4 + qg)];
            dst[0] = p;
            dst[1] = p;
        }
    }

    ull acco[8][2];
#pragma unroll
    for (int qi = 0; qi < 8; qi++) { acco[qi][0] = 0ull; acco[qi][1] = 0ull; }

    for (int kc4 = 0; kc4 < 8; kc4++) {
        __syncthreads();
#pragma unroll
        for (int it = 0; it < 8; it++) {
            int idx = it * 256 + t;
            int kil = idx >> 6, cg = idx & 63;
            int ki = kc4 * 32 + kil;
            int kr = ki / 14, kc = ki - 14 * kr;
            int kx = min(max(qx0 - 5 + kr, 0), 63);
            int ky = min(max(qy0 - 5 + kc, 0), 63);
            *(float4*)&KV[kil * 256 + cg * 4] =
                *(const float4*)&g_v[kvbase + (size_t)((kx << 6) + ky) * 256 + cg * 4];
        }
        __syncthreads();
#pragma unroll 4
        for (int kil = 0; kil < 32; kil++) {
            ulonglong2 vv = *(const ulonglong2*)&KV[kil * 256 + kg * 4];
            const float* prow = &Ps[(kc4 * 32 + kil) * PS_STRIDE];
#pragma unroll
            for (int qi = 0; qi < 8; qi++) {
                ull pd = *(const ull*)&prow[2 * (qi * 4 + qg)];
                acco[qi][0] = ffma2(pd, vv.x, acco[qi][0]);
                acco[qi][1] = ffma2(pd, vv.y, acco[qi][1]);
            }
        }
    }

#pragma unroll
    for (int qi = 0; qi < 8; qi++) {
        int nq = ((qx0 + qi) << 6) + qy0 + qg;
        ull* dst = (ull*)&g_ao[kvbase + (size_t)nq * 256 + kg * 4];
        dst[0] = acco[qi][0];
        dst[1] = acco[qi][1];
    }
}

// =====================================================================
// L6: fusion 1x1 conv -> d_out [b,128,64,64]
// =====================================================================
__global__ __launch_bounds__(128) void fusion_kernel(const float* __restrict__ b_f,
                                                     float* __restrict__ out) {
    __shared__ float sin_[256 * 36];
    int b = blockIdx.y, n0 = blockIdx.x * 32, tid = threadIdx.x;
    for (int idx = tid; idx < 32 * 256; idx += 128) {
        int p = idx >> 8, c = idx & 255;
        sin_[c * 36 + p] = g_ao[((size_t)b * NPIX + n0 + p) * 256 + c];
    }
    __syncthreads();
    ull acc[16];
    ull bo = fdup(b_f[tid]);
#pragma unroll
    for (int j = 0; j < 16; j++) acc[j] = bo;
#pragma unroll 4
    for (int c = 0; c < 256; c++) {
        ull w = *(const ull*)&g_wfD[c * 256 + 2 * tid];
        const float* row = &sin_[c * 36];
#pragma unroll
        for (int j = 0; j < 8; j++) {
            ulonglong2 v = *(const ulonglong2*)&row[j * 4];
            acc[2 * j] = ffma2(w, v.x, acc[2 * j]);
            acc[2 * j + 1] = ffma2(w, v.y, acc[2 * j + 1]);
        }
    }
    __syncthreads();
#pragma unroll
    for (int j = 0; j < 16; j++) {
        float2 f = u2f(acc[j]);
        sin_[tid * 33 + 2 * j] = f.x;
        sin_[tid * 33 + 2 * j + 1] = f.y;
    }
    __syncthreads();
    for (int idx = tid; idx < 128 * 32; idx += 128) {
        int o = idx >> 5, p = idx & 31;
        out[((size_t)(b * 128 + o)) * NPIX + n0 + p] = sin_[o * 33 + p];
    }
}

// ---------------- launch ----------------
extern "C" void kernel_launch(void* const* d_in, const int* in_sizes, int n_in,
                              void* d_out, int out_size) {
    const float* edge   = (const float*)d_in[0];
    const float* sem    = (const float*)d_in[1];
    const float* fusedf = (const float*)d_in[2];
    const float* w_al   = (const float*)d_in[3];
    const float* b_al   = (const float*)d_in[4];
    const float* w_fal  = (const float*)d_in[5];
    const float* b_fal  = (const float*)d_in[6];
    const float* w_q    = (const float*)d_in[7];
    const float* b_q    = (const float*)d_in[8];
    const float* w_k    = (const float*)d_in[9];
    const float* b_k    = (const float*)d_in[10];
    const float* w_f    = (const float*)d_in[11];
    const float* b_f    = (const float*)d_in[12];
    float* out = (float*)d_out;

    cudaFuncSetAttribute(attn_kernel, cudaFuncAttributeMaxDynamicSharedMemorySize,
                         ATTN_SMEM_BYTES);

    prep_conv_kernel<<<256 + 2048, 256>>>(w_q, w_k, w_f, edge, fusedf,
                                          w_al, b_al, w_fal, b_fal);
    upsample_sim_kernel<<<dim3(128, 4), 256>>>(sem);
    mid_kernel<<<512 + 4096 + 4, 256>>>(sem, b_q);
    qk_k_kernel<<<dim3(128, 4), 256>>>(sem, b_k);        // <- profile slot (#4)
    attn_kernel<<<dim3(128, 4), 256, ATTN_SMEM_BYTES>>>();
    fusion_kernel<<<dim3(128, 4), 128>>>(b_f, out);
}